// round 15
// baseline (speedup 1.0000x reference)
#include <cuda_runtime.h>
#include <math.h>
#include <stdint.h>

#define BSZ   2
#define TSEQ  2048
#define DMODEL 1024
#define NHEAD 16
#define DHEAD 64
#define MROWS (BSZ * TSEQ)   // 4096

// Scratch (allocation-free rule: __device__ globals)
__device__ float g_q[MROWS * DMODEL];
__device__ float g_k[MROWS * DMODEL];
__device__ float g_v[MROWS * DMODEL];
__device__ float g_attn[MROWS * DMODEL];

__device__ __forceinline__ float tf32r(float x) {
    asm("cvt.rna.tf32.f32 %0, %0;" : "+f"(x));
    return x;
}

__device__ __forceinline__ float ex2(float x) {
    float r;
    asm("ex2.approx.ftz.f32 %0, %1;" : "=f"(r) : "f"(x));
    return r;
}

__device__ __forceinline__ void mma_tf32(float* c, const uint32_t* a, const uint32_t* b) {
    asm volatile(
        "mma.sync.aligned.m16n8k8.row.col.f32.tf32.tf32.f32 "
        "{%0,%1,%2,%3}, {%4,%5,%6,%7}, {%8,%9}, {%0,%1,%2,%3};"
        : "+f"(c[0]), "+f"(c[1]), "+f"(c[2]), "+f"(c[3])
        : "r"(a[0]), "r"(a[1]), "r"(a[2]), "r"(a[3]), "r"(b[0]), "r"(b[1]));
}

// ===========================================================================
// Software-pipelined tensor-core GEMM (tf32): C = A[M,K] @ W[N,K]^T + bias
// Round-7 numerics (cvt.rna at staging -- REQUIRED). Batched over blockIdx.z.
// 2 smem stages + 16-reg prefetch, 1 barrier/chunk; LDG overlapped with MMAs.
// Dynamic smem: 2 x (As 128x36 + Ws 128x36) = 73,728 B; 2 CTAs/SM.
// ===========================================================================
#define GSTAGE_FLOATS (2 * 128 * 36)             // 9216 floats per stage
#define GEMM_SMEM_BYTES (2 * GSTAGE_FLOATS * 4)  // 73,728 B

__global__ __launch_bounds__(256, 2) void gemm3_mma_kernel(
    const float* __restrict__ A0, const float* __restrict__ W0,
    const float* __restrict__ b0, float* __restrict__ C0,
    const float* __restrict__ A1, const float* __restrict__ W1,
    const float* __restrict__ b1, float* __restrict__ C1,
    const float* __restrict__ A2, const float* __restrict__ W2,
    const float* __restrict__ b2, float* __restrict__ C2)
{
    extern __shared__ float dsm[];

    const int bz = blockIdx.z;
    const float* A    = (bz == 0) ? A0 : (bz == 1) ? A1 : A2;
    const float* W    = (bz == 0) ? W0 : (bz == 1) ? W1 : W2;
    const float* bias = (bz == 0) ? b0 : (bz == 1) ? b1 : b2;
    float*       C    = (bz == 0) ? C0 : (bz == 1) ? C1 : C2;

    const int tid = threadIdx.x;
    const int wid = tid >> 5;
    const int lid = tid & 31;
    const int bn  = blockIdx.x * 128;
    const int bm  = blockIdx.y * 128;
    const int wm  = (wid >> 2) * 64;
    const int wn  = (wid & 3) * 32;
    const int g   = lid >> 2;
    const int tig = lid & 3;

    // Per-thread staging coordinates (4 float4 per tensor per chunk).
    const int srow = tid >> 3;            // 0..31  (row base; +32 per i)
    const int sc4  = (tid & 7) << 2;      // 0,4,..,28

    float acc[4][4][4];
#pragma unroll
    for (int mi = 0; mi < 4; mi++)
#pragma unroll
        for (int ni = 0; ni < 4; ni++)
#pragma unroll
            for (int r = 0; r < 4; r++) acc[mi][ni][r] = 0.0f;

    // ---- prologue: stage chunk 0 into buffer 0 (A then W, 16 regs) ----
    {
        float4 ra[4];
#pragma unroll
        for (int i = 0; i < 4; i++)
            ra[i] = *(const float4*)(A + (size_t)(bm + srow + i * 32) * DMODEL + sc4);
#pragma unroll
        for (int i = 0; i < 4; i++) {
            ra[i].x = tf32r(ra[i].x); ra[i].y = tf32r(ra[i].y);
            ra[i].z = tf32r(ra[i].z); ra[i].w = tf32r(ra[i].w);
            *(float4*)&dsm[(srow + i * 32) * 36 + sc4] = ra[i];
        }
#pragma unroll
        for (int i = 0; i < 4; i++)
            ra[i] = *(const float4*)(W + (size_t)(bn + srow + i * 32) * DMODEL + sc4);
#pragma unroll
        for (int i = 0; i < 4; i++) {
            ra[i].x = tf32r(ra[i].x); ra[i].y = tf32r(ra[i].y);
            ra[i].z = tf32r(ra[i].z); ra[i].w = tf32r(ra[i].w);
            *(float4*)&dsm[128 * 36 + (srow + i * 32) * 36 + sc4] = ra[i];
        }
    }
    __syncthreads();

    for (int c = 0; c < 32; c++) {
        const int s = c & 1;
        const float* As = dsm + s * GSTAGE_FLOATS;
        const float* Ws = As + 128 * 36;
        float* Ad = dsm + (s ^ 1) * GSTAGE_FLOATS;
        float* Wd = Ad + 128 * 36;
        const bool pf = (c + 1 < 32);
        const int kn = (c + 1) * 32;

        float4 ra[4];
        if (pf) {
#pragma unroll
            for (int i = 0; i < 4; i++)
                ra[i] = *(const float4*)(A + (size_t)(bm + srow + i * 32) * DMODEL + kn + sc4);
        }

        // ---- compute kk = 0..15 (LDG A latency hidden) ----
#pragma unroll
        for (int kk = 0; kk < 16; kk += 8) {
            uint32_t af[4][4], bf[4][2];
#pragma unroll
            for (int mi = 0; mi < 4; mi++) {
                const int m = wm + mi * 16 + g;
                af[mi][0] = __float_as_uint(As[m * 36 + kk + tig]);
                af[mi][1] = __float_as_uint(As[(m + 8) * 36 + kk + tig]);
                af[mi][2] = __float_as_uint(As[m * 36 + kk + tig + 4]);
                af[mi][3] = __float_as_uint(As[(m + 8) * 36 + kk + tig + 4]);
            }
#pragma unroll
            for (int ni = 0; ni < 4; ni++) {
                const int n = wn + ni * 8 + g;
                bf[ni][0] = __float_as_uint(Ws[n * 36 + kk + tig]);
                bf[ni][1] = __float_as_uint(Ws[n * 36 + kk + tig + 4]);
            }
#pragma unroll
            for (int mi = 0; mi < 4; mi++)
#pragma unroll
                for (int ni = 0; ni < 4; ni++)
                    mma_tf32(acc[mi][ni], af[mi], bf[ni]);
        }

        if (pf) {
            // Drain A prefetch into next stage; start W prefetch (reuse regs).
#pragma unroll
            for (int i = 0; i < 4; i++) {
                ra[i].x = tf32r(ra[i].x); ra[i].y = tf32r(ra[i].y);
                ra[i].z = tf32r(ra[i].z); ra[i].w = tf32r(ra[i].w);
                *(float4*)&Ad[(srow + i * 32) * 36 + sc4] = ra[i];
            }
#pragma unroll
            for (int i = 0; i < 4; i++)
                ra[i] = *(const float4*)(W + (size_t)(bn + srow + i * 32) * DMODEL + kn + sc4);
        }

        // ---- compute kk = 16..31 (LDG W latency hidden) ----
#pragma unroll
        for (int kk = 16; kk < 32; kk += 8) {
            uint32_t af[4][4], bf[4][2];
#pragma unroll
            for (int mi = 0; mi < 4; mi++) {
                const int m = wm + mi * 16 + g;
                af[mi][0] = __float_as_uint(As[m * 36 + kk + tig]);
                af[mi][1] = __float_as_uint(As[(m + 8) * 36 + kk + tig]);
                af[mi][2] = __float_as_uint(As[m * 36 + kk + tig + 4]);
                af[mi][3] = __float_as_uint(As[(m + 8) * 36 + kk + tig + 4]);
            }
#pragma unroll
            for (int ni = 0; ni < 4; ni++) {
                const int n = wn + ni * 8 + g;
                bf[ni][0] = __float_as_uint(Ws[n * 36 + kk + tig]);
                bf[ni][1] = __float_as_uint(Ws[n * 36 + kk + tig + 4]);
            }
#pragma unroll
            for (int mi = 0; mi < 4; mi++)
#pragma unroll
                for (int ni = 0; ni < 4; ni++)
                    mma_tf32(acc[mi][ni], af[mi], bf[ni]);
        }

        if (pf) {
#pragma unroll
            for (int i = 0; i < 4; i++) {
                ra[i].x = tf32r(ra[i].x); ra[i].y = tf32r(ra[i].y);
                ra[i].z = tf32r(ra[i].z); ra[i].w = tf32r(ra[i].w);
                *(float4*)&Wd[(srow + i * 32) * 36 + sc4] = ra[i];
            }
        }
        __syncthreads();   // stage s consumed + stage s^1 filled
    }

#pragma unroll
    for (int ni = 0; ni < 4; ni++) {
        const int n = bn + wn + ni * 8 + 2 * tig;
        const float bb0 = bias[n], bb1 = bias[n + 1];
#pragma unroll
        for (int mi = 0; mi < 4; mi++) {
            const int m0 = bm + wm + mi * 16 + g;
            float2 lo = make_float2(acc[mi][ni][0] + bb0, acc[mi][ni][1] + bb1);
            float2 hi = make_float2(acc[mi][ni][2] + bb0, acc[mi][ni][3] + bb1);
            *(float2*)(C + (size_t)m0 * DMODEL + n)       = lo;
            *(float2*)(C + (size_t)(m0 + 8) * DMODEL + n) = hi;
        }
    }
}

// ===========================================================================
// Causal flash attention, FA2-style, 2 CTAs/SM + LPT (round-14, ~250us).
// ===========================================================================
#define FPITCH 68
#define FQS_OFF 0                  // Qs[128][68]  natural [q][d], pre-scaled
#define FKS_OFF (128 * FPITCH)     // Ks[64][68]   natural [k][d]
#define FVS_OFF (192 * FPITCH)     // Vs[64][68]   transposed [d][k]
#define FPS_OFF (256 * FPITCH)     // Ps[128][68]  per-warp P slabs
#define FATTN_SMEM_BYTES ((384 * FPITCH) * 4)   // 104,448 B

__global__ __launch_bounds__(256, 2) void attn_fa2_kernel(
    const float* __restrict__ Q, const float* __restrict__ K,
    const float* __restrict__ V, float* __restrict__ O)
{
    extern __shared__ float sm[];
    float* Qs = sm + FQS_OFF;
    float* Ks = sm + FKS_OFF;
    float* Vs = sm + FVS_OFF;
    float* Ps = sm + FPS_OFF;

    // LPT: invert qt so the heaviest (most key-tiles) blocks start first.
    const int qt  = (gridDim.x - 1) - blockIdx.x;
    const int h   = blockIdx.y;
    const int b   = blockIdx.z;
    const int tid = threadIdx.x;
    const int wid = tid >> 5;
    const int lid = tid & 31;
    const int g   = lid >> 2;
    const int tig = lid & 3;
    const int wm  = wid * 16;          // this warp's 16 query rows
    const int q0  = qt * 128;

    const float SC = 0.18033688011f;   // (1/sqrt(64)) * log2(e)
    const float* Qg = Q + (size_t)(b * TSEQ + q0 + wm) * DMODEL + h * DHEAD;
#pragma unroll
    for (int i = 0; i < 8; i++) {
        int v   = i * 32 + lid;
        int row = v >> 4;
        int c4  = (v & 15) << 2;
        float4 t = *(const float4*)(Qg + (size_t)row * DMODEL + c4);
        t.x = tf32r(t.x * SC); t.y = tf32r(t.y * SC);
        t.z = tf32r(t.z * SC); t.w = tf32r(t.w * SC);
        *(float4*)&Qs[(wm + row) * FPITCH + c4] = t;
    }
    __syncwarp();

    float acc[8][4];
#pragma unroll
    for (int ni = 0; ni < 8; ni++)
#pragma unroll
        for (int r = 0; r < 4; r++) acc[ni][r] = 0.0f;

    float m0 = -1e30f, m1 = -1e30f, l0 = 0.0f, l1 = 0.0f;
    const int row0 = q0 + wm + g;

    const int n_kt = 2 * qt + 2;
    for (int kt = 0; kt < n_kt; kt++) {
        __syncthreads();
        const float* Kg = K + (size_t)(b * TSEQ + kt * 64) * DMODEL + h * DHEAD;
        const float* Vg = V + (size_t)(b * TSEQ + kt * 64) * DMODEL + h * DHEAD;
#pragma unroll
        for (int i = 0; i < 4; i++) {
            int v  = i * 256 + tid;
            int kr = v >> 4;
            int d4 = (v & 15) << 2;
            float4 t = *(const float4*)(Kg + (size_t)kr * DMODEL + d4);
            t.x = tf32r(t.x); t.y = tf32r(t.y); t.z = tf32r(t.z); t.w = tf32r(t.w);
            *(float4*)&Ks[kr * FPITCH + d4] = t;
            float4 u = *(const float4*)(Vg + (size_t)kr * DMODEL + d4);
            Vs[(d4 + 0) * FPITCH + kr] = tf32r(u.x);
            Vs[(d4 + 1) * FPITCH + kr] = tf32r(u.y);
            Vs[(d4 + 2) * FPITCH + kr] = tf32r(u.z);
            Vs[(d4 + 3) * FPITCH + kr] = tf32r(u.w);
        }
        __syncthreads();

        float sacc[8][4];
#pragma unroll
        for (int ni = 0; ni < 8; ni++)
#pragma unroll
            for (int r = 0; r < 4; r++) sacc[ni][r] = 0.0f;

#pragma unroll
        for (int kk = 0; kk < 8; kk++) {
            uint32_t af[4];
            af[0] = __float_as_uint(Qs[(wm + g) * FPITCH + kk * 8 + tig]);
            af[1] = __float_as_uint(Qs[(wm + g + 8) * FPITCH + kk * 8 + tig]);
            af[2] = __float_as_uint(Qs[(wm + g) * FPITCH + kk * 8 + tig + 4]);
            af[3] = __float_as_uint(Qs[(wm + g + 8) * FPITCH + kk * 8 + tig + 4]);
#pragma unroll
            for (int ni = 0; ni < 8; ni++) {
                uint32_t bf[2];
                bf[0] = __float_as_uint(Ks[(ni * 8 + g) * FPITCH + kk * 8 + tig]);
                bf[1] = __float_as_uint(Ks[(ni * 8 + g) * FPITCH + kk * 8 + tig + 4]);
                mma_tf32(sacc[ni], af, bf);
            }
        }

        const int lim0 = row0 - kt * 64;
        const int lim1 = lim0 + 8;
#pragma unroll
        for (int ni = 0; ni < 8; ni++) {
            const int c0 = ni * 8 + 2 * tig;
            const int c1 = c0 + 1;
            if (c0 > lim0) sacc[ni][0] = -1e30f;
            if (c1 > lim0) sacc[ni][1] = -1e30f;
            if (c0 > lim1) sacc[ni][2] = -1e30f;
            if (c1 > lim1) sacc[ni][3] = -1e30f;
        }

        float mx0 = -1e30f, mx1 = -1e30f;
#pragma unroll
        for (int ni = 0; ni < 8; ni++) {
            mx0 = fmaxf(mx0, fmaxf(sacc[ni][0], sacc[ni][1]));
            mx1 = fmaxf(mx1, fmaxf(sacc[ni][2], sacc[ni][3]));
        }
        mx0 = fmaxf(mx0, __shfl_xor_sync(0xffffffffu, mx0, 1));
        mx0 = fmaxf(mx0, __shfl_xor_sync(0xffffffffu, mx0, 2));
        mx1 = fmaxf(mx1, __shfl_xor_sync(0xffffffffu, mx1, 1));
        mx1 = fmaxf(mx1, __shfl_xor_sync(0xffffffffu, mx1, 2));

        const float mn0 = fmaxf(m0, mx0);
        const float mn1 = fmaxf(m1, mx1);
        const float a0 = ex2(m0 - mn0);
        const float a1 = ex2(m1 - mn1);
        float ls0 = 0.0f, ls1 = 0.0f;
#pragma unroll
        for (int ni = 0; ni < 8; ni++) {
            float p0 = tf32r(ex2(sacc[ni][0] - mn0));
            float p1 = tf32r(ex2(sacc[ni][1] - mn0));
            float p2 = tf32r(ex2(sacc[ni][2] - mn1));
            float p3 = tf32r(ex2(sacc[ni][3] - mn1));
            sacc[ni][0] = p0; sacc[ni][1] = p1;
            sacc[ni][2] = p2; sacc[ni][3] = p3;
            ls0 += p0 + p1;
            ls1 += p2 + p3;
        }
        ls0 += __shfl_xor_sync(0xffffffffu, ls0, 1);
        ls0 += __shfl_xor_sync(0xffffffffu, ls0, 2);
        ls1 += __shfl_xor_sync(0xffffffffu, ls1, 1);
        ls1 += __shfl_xor_sync(0xffffffffu, ls1, 2);
        l0 = l0 * a0 + ls0;
        l1 = l1 * a1 + ls1;
        m0 = mn0; m1 = mn1;

#pragma unroll
        for (int ni = 0; ni < 8; ni++) {
            acc[ni][0] *= a0; acc[ni][1] *= a0;
            acc[ni][2] *= a1; acc[ni][3] *= a1;
        }

#pragma unroll
        for (int ni = 0; ni < 8; ni++) {
            *(float2*)&Ps[(wm + g) * FPITCH + ni * 8 + 2 * tig] =
                make_float2(sacc[ni][0], sacc[ni][1]);
            *(float2*)&Ps[(wm + g + 8) * FPITCH + ni * 8 + 2 * tig] =
                make_float2(sacc[ni][2], sacc[ni][3]);
        }
        __syncwarp();

#pragma unroll
        for (int kk = 0; kk < 8; kk++) {
            uint32_t af[4];
            af[0] = __float_as_uint(Ps[(wm + g) * FPITCH + kk * 8 + tig]);
            af[1] = __float_as_uint(Ps[(wm + g + 8) * FPITCH + kk * 8 + tig]);
            af[2] = __float_as_uint(Ps[(wm + g) * FPITCH + kk * 8 + tig + 4]);
            af[3] = __float_as_uint(Ps[(wm + g + 8) * FPITCH + kk * 8 + tig + 4]);
#pragma unroll
            for (int ni = 0; ni < 8; ni++) {
                uint32_t bf[2];
                bf[0] = __float_as_uint(Vs[(ni * 8 + g) * FPITCH + kk * 8 + tig]);
                bf[1] = __float_as_uint(Vs[(ni * 8 + g) * FPITCH + kk * 8 + tig + 4]);
                mma_tf32(acc[ni], af, bf);
            }
        }
        __syncwarp();
    }

    const float inv0 = 1.0f / l0;
    const float inv1 = 1.0f / l1;
    float* Og = O + (size_t)(b * TSEQ + q0 + wm) * DMODEL + h * DHEAD;
#pragma unroll
    for (int ni = 0; ni < 8; ni++) {
        const int n = ni * 8 + 2 * tig;
        *(float2*)(Og + (size_t)g * DMODEL + n) =
            make_float2(acc[ni][0] * inv0, acc[ni][1] * inv0);
        *(float2*)(Og + (size_t)(g + 8) * DMODEL + n) =
            make_float2(acc[ni][2] * inv1, acc[ni][3] * inv1);
    }
}

// ---------------------------------------------------------------------------
extern "C" void kernel_launch(void* const* d_in, const int* in_sizes, int n_in,
                              void* d_out, int out_size)
{
    (void)in_sizes; (void)n_in; (void)out_size;
    const float* query = (const float*)d_in[0];
    const float* key_  = (const float*)d_in[1];
    const float* value = (const float*)d_in[2];
    const float* q_w   = (const float*)d_in[3];
    const float* q_b   = (const float*)d_in[4];
    const float* k_w   = (const float*)d_in[5];
    const float* k_b   = (const float*)d_in[6];
    const float* v_w   = (const float*)d_in[7];
    const float* v_b   = (const float*)d_in[8];
    const float* o_w   = (const float*)d_in[9];
    const float* o_b   = (const float*)d_in[10];
    float* out = (float*)d_out;

    float *qp, *kp, *vp, *ap;
    cudaGetSymbolAddress((void**)&qp, g_q);
    cudaGetSymbolAddress((void**)&kp, g_k);
    cudaGetSymbolAddress((void**)&vp, g_v);
    cudaGetSymbolAddress((void**)&ap, g_attn);

    cudaFuncSetAttribute(gemm3_mma_kernel,
                         cudaFuncAttributeMaxDynamicSharedMemorySize,
                         GEMM_SMEM_BYTES);
    cudaFuncSetAttribute(attn_fa2_kernel,
                         cudaFuncAttributeMaxDynamicSharedMemorySize,
                         FATTN_SMEM_BYTES);

    // QKV projections: one batched launch (z = 0,1,2).
    gemm3_mma_kernel<<<dim3(8, 32, 3), 256, GEMM_SMEM_BYTES>>>(
        query, q_w, q_b, qp,
        key_,  k_w, k_b, kp,
        value, v_w, v_b, vp);

    attn_fa2_kernel<<<dim3(TSEQ / 128, NHEAD, BSZ), 256, FATTN_SMEM_BYTES>>>(qp, kp, vp, ap);

    // Output projection (z = 0 only).
    gemm3_mma_kernel<<<dim3(8, 32, 1), 256, GEMM_SMEM_BYTES>>>(
        ap, o_w, o_b, out,
        ap, o_w, o_b, out,
        ap, o_w, o_b, out);
}

// round 16
// speedup vs baseline: 1.5457x; 1.5457x over previous
#include <cuda_runtime.h>
#include <math.h>
#include <stdint.h>

#define BSZ   2
#define TSEQ  2048
#define DMODEL 1024
#define NHEAD 16
#define DHEAD 64
#define MROWS (BSZ * TSEQ)   // 4096

// Scratch (allocation-free rule: __device__ globals)
__device__ float g_q[MROWS * DMODEL];
__device__ float g_k[MROWS * DMODEL];
__device__ float g_v[MROWS * DMODEL];
__device__ float g_attn[MROWS * DMODEL];

__device__ __forceinline__ float tf32r(float x) {
    asm("cvt.rna.tf32.f32 %0, %0;" : "+f"(x));
    return x;
}

__device__ __forceinline__ float ex2(float x) {
    float r;
    asm("ex2.approx.ftz.f32 %0, %1;" : "=f"(r) : "f"(x));
    return r;
}

__device__ __forceinline__ void mma_tf32(float* c, const uint32_t* a, const uint32_t* b) {
    asm volatile(
        "mma.sync.aligned.m16n8k8.row.col.f32.tf32.tf32.f32 "
        "{%0,%1,%2,%3}, {%4,%5,%6,%7}, {%8,%9}, {%0,%1,%2,%3};"
        : "+f"(c[0]), "+f"(c[1]), "+f"(c[2]), "+f"(c[3])
        : "r"(a[0]), "r"(a[1]), "r"(a[2]), "r"(a[3]), "r"(b[0]), "r"(b[1]));
}

// ===========================================================================
// Tensor-core GEMM (tf32), BK=64: C = A[M,K] @ W[N,K]^T + bias
// Round-14 body/numerics (cvt.rna at staging -- REQUIRED), but 16 chunks of
// K=64 instead of 32 of K=32: halves the number of staging-stall + barrier
// events per CTA. Distance-1 L2 prefetch for the next chunk.
// Pitch 68: fragment LDS conflict-free, float4 STS at 2-phase minimum.
// Dynamic smem: 2 x 128 x 68 floats = 69,632 B; 2 CTAs/SM.
// ===========================================================================
#define GPITCH 68
#define GTENSOR_FLOATS (128 * GPITCH)              // 8704
#define GEMM_SMEM_BYTES (2 * GTENSOR_FLOATS * 4)   // 69,632 B

__global__ __launch_bounds__(256, 2) void gemm3_mma_kernel(
    const float* __restrict__ A0, const float* __restrict__ W0,
    const float* __restrict__ b0, float* __restrict__ C0,
    const float* __restrict__ A1, const float* __restrict__ W1,
    const float* __restrict__ b1, float* __restrict__ C1,
    const float* __restrict__ A2, const float* __restrict__ W2,
    const float* __restrict__ b2, float* __restrict__ C2)
{
    extern __shared__ float dsm[];
    float* As = dsm;
    float* Ws = dsm + GTENSOR_FLOATS;

    const int bz = blockIdx.z;
    const float* A    = (bz == 0) ? A0 : (bz == 1) ? A1 : A2;
    const float* W    = (bz == 0) ? W0 : (bz == 1) ? W1 : W2;
    const float* bias = (bz == 0) ? b0 : (bz == 1) ? b1 : b2;
    float*       C    = (bz == 0) ? C0 : (bz == 1) ? C1 : C2;

    const int tid = threadIdx.x;
    const int wid = tid >> 5;
    const int lid = tid & 31;
    const int bn  = blockIdx.x * 128;
    const int bm  = blockIdx.y * 128;
    const int wm  = (wid >> 2) * 64;
    const int wn  = (wid & 3) * 32;
    const int g   = lid >> 2;
    const int tig = lid & 3;

    float acc[4][4][4];
#pragma unroll
    for (int mi = 0; mi < 4; mi++)
#pragma unroll
        for (int ni = 0; ni < 4; ni++)
#pragma unroll
            for (int r = 0; r < 4; r++) acc[mi][ni][r] = 0.0f;

    // L2 prefetch coordinates: 512 128B-lines per chunk (128 rows x 2 lines
    // x 2 tensors); 256 threads x 2 prefetches.
    const int prow = tid >> 1;
    const int pcol = (tid & 1) << 5;   // 0 or 32 (floats)

    for (int k0 = 0; k0 < DMODEL; k0 += 64) {
        if (k0) __syncthreads();
        // Stage chunk: 128 rows x 64 cols per tensor, 8 float4 per thread.
#pragma unroll
        for (int i = 0; i < 8; i++) {
            int v   = i * 256 + tid;    // 0..2047
            int row = v >> 4;           // 0..127
            int c4  = (v & 15) << 2;    // 0..60
            float4 a = *(const float4*)(A + (size_t)(bm + row) * DMODEL + k0 + c4);
            a.x = tf32r(a.x); a.y = tf32r(a.y); a.z = tf32r(a.z); a.w = tf32r(a.w);
            *(float4*)&As[row * GPITCH + c4] = a;
            float4 w = *(const float4*)(W + (size_t)(bn + row) * DMODEL + k0 + c4);
            w.x = tf32r(w.x); w.y = tf32r(w.y); w.z = tf32r(w.z); w.w = tf32r(w.w);
            *(float4*)&Ws[row * GPITCH + c4] = w;
        }
        // Prefetch next chunk to L2 (fire-and-forget; no register residency).
        if (k0 + 64 < DMODEL) {
            asm volatile("prefetch.global.L2 [%0];"
                         :: "l"(A + (size_t)(bm + prow) * DMODEL + k0 + 64 + pcol));
            asm volatile("prefetch.global.L2 [%0];"
                         :: "l"(W + (size_t)(bn + prow) * DMODEL + k0 + 64 + pcol));
        }
        __syncthreads();

#pragma unroll
        for (int kk = 0; kk < 64; kk += 8) {
            uint32_t af[4][4], bf[4][2];
#pragma unroll
            for (int mi = 0; mi < 4; mi++) {
                const int m = wm + mi * 16 + g;
                af[mi][0] = __float_as_uint(As[m * GPITCH + kk + tig]);
                af[mi][1] = __float_as_uint(As[(m + 8) * GPITCH + kk + tig]);
                af[mi][2] = __float_as_uint(As[m * GPITCH + kk + tig + 4]);
                af[mi][3] = __float_as_uint(As[(m + 8) * GPITCH + kk + tig + 4]);
            }
#pragma unroll
            for (int ni = 0; ni < 4; ni++) {
                const int n = wn + ni * 8 + g;
                bf[ni][0] = __float_as_uint(Ws[n * GPITCH + kk + tig]);
                bf[ni][1] = __float_as_uint(Ws[n * GPITCH + kk + tig + 4]);
            }
#pragma unroll
            for (int mi = 0; mi < 4; mi++)
#pragma unroll
                for (int ni = 0; ni < 4; ni++)
                    mma_tf32(acc[mi][ni], af[mi], bf[ni]);
        }
    }

#pragma unroll
    for (int ni = 0; ni < 4; ni++) {
        const int n = bn + wn + ni * 8 + 2 * tig;
        const float bb0 = bias[n], bb1 = bias[n + 1];
#pragma unroll
        for (int mi = 0; mi < 4; mi++) {
            const int m0 = bm + wm + mi * 16 + g;
            float2 lo = make_float2(acc[mi][ni][0] + bb0, acc[mi][ni][1] + bb1);
            float2 hi = make_float2(acc[mi][ni][2] + bb0, acc[mi][ni][3] + bb1);
            *(float2*)(C + (size_t)m0 * DMODEL + n)       = lo;
            *(float2*)(C + (size_t)(m0 + 8) * DMODEL + n) = hi;
        }
    }
}

// ===========================================================================
// Causal flash attention, FA2-style, 2 CTAs/SM + LPT (round-14, unchanged).
// ===========================================================================
#define FPITCH 68
#define FQS_OFF 0                  // Qs[128][68]  natural [q][d], pre-scaled
#define FKS_OFF (128 * FPITCH)     // Ks[64][68]   natural [k][d]
#define FVS_OFF (192 * FPITCH)     // Vs[64][68]   transposed [d][k]
#define FPS_OFF (256 * FPITCH)     // Ps[128][68]  per-warp P slabs
#define FATTN_SMEM_BYTES ((384 * FPITCH) * 4)   // 104,448 B

__global__ __launch_bounds__(256, 2) void attn_fa2_kernel(
    const float* __restrict__ Q, const float* __restrict__ K,
    const float* __restrict__ V, float* __restrict__ O)
{
    extern __shared__ float sm[];
    float* Qs = sm + FQS_OFF;
    float* Ks = sm + FKS_OFF;
    float* Vs = sm + FVS_OFF;
    float* Ps = sm + FPS_OFF;

    const int qt  = (gridDim.x - 1) - blockIdx.x;   // LPT: heavy tiles first
    const int h   = blockIdx.y;
    const int b   = blockIdx.z;
    const int tid = threadIdx.x;
    const int wid = tid >> 5;
    const int lid = tid & 31;
    const int g   = lid >> 2;
    const int tig = lid & 3;
    const int wm  = wid * 16;
    const int q0  = qt * 128;

    const float SC = 0.18033688011f;   // (1/sqrt(64)) * log2(e)
    const float* Qg = Q + (size_t)(b * TSEQ + q0 + wm) * DMODEL + h * DHEAD;
#pragma unroll
    for (int i = 0; i < 8; i++) {
        int v   = i * 32 + lid;
        int row = v >> 4;
        int c4  = (v & 15) << 2;
        float4 t = *(const float4*)(Qg + (size_t)row * DMODEL + c4);
        t.x = tf32r(t.x * SC); t.y = tf32r(t.y * SC);
        t.z = tf32r(t.z * SC); t.w = tf32r(t.w * SC);
        *(float4*)&Qs[(wm + row) * FPITCH + c4] = t;
    }
    __syncwarp();

    float acc[8][4];
#pragma unroll
    for (int ni = 0; ni < 8; ni++)
#pragma unroll
        for (int r = 0; r < 4; r++) acc[ni][r] = 0.0f;

    float m0 = -1e30f, m1 = -1e30f, l0 = 0.0f, l1 = 0.0f;
    const int row0 = q0 + wm + g;

    const int n_kt = 2 * qt + 2;
    for (int kt = 0; kt < n_kt; kt++) {
        __syncthreads();
        const float* Kg = K + (size_t)(b * TSEQ + kt * 64) * DMODEL + h * DHEAD;
        const float* Vg = V + (size_t)(b * TSEQ + kt * 64) * DMODEL + h * DHEAD;
#pragma unroll
        for (int i = 0; i < 4; i++) {
            int v  = i * 256 + tid;
            int kr = v >> 4;
            int d4 = (v & 15) << 2;
            float4 t = *(const float4*)(Kg + (size_t)kr * DMODEL + d4);
            t.x = tf32r(t.x); t.y = tf32r(t.y); t.z = tf32r(t.z); t.w = tf32r(t.w);
            *(float4*)&Ks[kr * FPITCH + d4] = t;
            float4 u = *(const float4*)(Vg + (size_t)kr * DMODEL + d4);
            Vs[(d4 + 0) * FPITCH + kr] = tf32r(u.x);
            Vs[(d4 + 1) * FPITCH + kr] = tf32r(u.y);
            Vs[(d4 + 2) * FPITCH + kr] = tf32r(u.z);
            Vs[(d4 + 3) * FPITCH + kr] = tf32r(u.w);
        }
        __syncthreads();

        float sacc[8][4];
#pragma unroll
        for (int ni = 0; ni < 8; ni++)
#pragma unroll
            for (int r = 0; r < 4; r++) sacc[ni][r] = 0.0f;

#pragma unroll
        for (int kk = 0; kk < 8; kk++) {
            uint32_t af[4];
            af[0] = __float_as_uint(Qs[(wm + g) * FPITCH + kk * 8 + tig]);
            af[1] = __float_as_uint(Qs[(wm + g + 8) * FPITCH + kk * 8 + tig]);
            af[2] = __float_as_uint(Qs[(wm + g) * FPITCH + kk * 8 + tig + 4]);
            af[3] = __float_as_uint(Qs[(wm + g + 8) * FPITCH + kk * 8 + tig + 4]);
#pragma unroll
            for (int ni = 0; ni < 8; ni++) {
                uint32_t bf[2];
                bf[0] = __float_as_uint(Ks[(ni * 8 + g) * FPITCH + kk * 8 + tig]);
                bf[1] = __float_as_uint(Ks[(ni * 8 + g) * FPITCH + kk * 8 + tig + 4]);
                mma_tf32(sacc[ni], af, bf);
            }
        }

        const int lim0 = row0 - kt * 64;
        const int lim1 = lim0 + 8;
#pragma unroll
        for (int ni = 0; ni < 8; ni++) {
            const int c0 = ni * 8 + 2 * tig;
            const int c1 = c0 + 1;
            if (c0 > lim0) sacc[ni][0] = -1e30f;
            if (c1 > lim0) sacc[ni][1] = -1e30f;
            if (c0 > lim1) sacc[ni][2] = -1e30f;
            if (c1 > lim1) sacc[ni][3] = -1e30f;
        }

        float mx0 = -1e30f, mx1 = -1e30f;
#pragma unroll
        for (int ni = 0; ni < 8; ni++) {
            mx0 = fmaxf(mx0, fmaxf(sacc[ni][0], sacc[ni][1]));
            mx1 = fmaxf(mx1, fmaxf(sacc[ni][2], sacc[ni][3]));
        }
        mx0 = fmaxf(mx0, __shfl_xor_sync(0xffffffffu, mx0, 1));
        mx0 = fmaxf(mx0, __shfl_xor_sync(0xffffffffu, mx0, 2));
        mx1 = fmaxf(mx1, __shfl_xor_sync(0xffffffffu, mx1, 1));
        mx1 = fmaxf(mx1, __shfl_xor_sync(0xffffffffu, mx1, 2));

        const float mn0 = fmaxf(m0, mx0);
        const float mn1 = fmaxf(m1, mx1);
        const float a0 = ex2(m0 - mn0);
        const float a1 = ex2(m1 - mn1);
        float ls0 = 0.0f, ls1 = 0.0f;
#pragma unroll
        for (int ni = 0; ni < 8; ni++) {
            float p0 = tf32r(ex2(sacc[ni][0] - mn0));
            float p1 = tf32r(ex2(sacc[ni][1] - mn0));
            float p2 = tf32r(ex2(sacc[ni][2] - mn1));
            float p3 = tf32r(ex2(sacc[ni][3] - mn1));
            sacc[ni][0] = p0; sacc[ni][1] = p1;
            sacc[ni][2] = p2; sacc[ni][3] = p3;
            ls0 += p0 + p1;
            ls1 += p2 + p3;
        }
        ls0 += __shfl_xor_sync(0xffffffffu, ls0, 1);
        ls0 += __shfl_xor_sync(0xffffffffu, ls0, 2);
        ls1 += __shfl_xor_sync(0xffffffffu, ls1, 1);
        ls1 += __shfl_xor_sync(0xffffffffu, ls1, 2);
        l0 = l0 * a0 + ls0;
        l1 = l1 * a1 + ls1;
        m0 = mn0; m1 = mn1;

#pragma unroll
        for (int ni = 0; ni < 8; ni++) {
            acc[ni][0] *= a0; acc[ni][1] *= a0;
            acc[ni][2] *= a1; acc[ni][3] *= a1;
        }

#pragma unroll
        for (int ni = 0; ni < 8; ni++) {
            *(float2*)&Ps[(wm + g) * FPITCH + ni * 8 + 2 * tig] =
                make_float2(sacc[ni][0], sacc[ni][1]);
            *(float2*)&Ps[(wm + g + 8) * FPITCH + ni * 8 + 2 * tig] =
                make_float2(sacc[ni][2], sacc[ni][3]);
        }
        __syncwarp();

#pragma unroll
        for (int kk = 0; kk < 8; kk++) {
            uint32_t af[4];
            af[0] = __float_as_uint(Ps[(wm + g) * FPITCH + kk * 8 + tig]);
            af[1] = __float_as_uint(Ps[(wm + g + 8) * FPITCH + kk * 8 + tig]);
            af[2] = __float_as_uint(Ps[(wm + g) * FPITCH + kk * 8 + tig + 4]);
            af[3] = __float_as_uint(Ps[(wm + g + 8) * FPITCH + kk * 8 + tig + 4]);
#pragma unroll
            for (int ni = 0; ni < 8; ni++) {
                uint32_t bf[2];
                bf[0] = __float_as_uint(Vs[(ni * 8 + g) * FPITCH + kk * 8 + tig]);
                bf[1] = __float_as_uint(Vs[(ni * 8 + g) * FPITCH + kk * 8 + tig + 4]);
                mma_tf32(acc[ni], af, bf);
            }
        }
        __syncwarp();
    }

    const float inv0 = 1.0f / l0;
    const float inv1 = 1.0f / l1;
    float* Og = O + (size_t)(b * TSEQ + q0 + wm) * DMODEL + h * DHEAD;
#pragma unroll
    for (int ni = 0; ni < 8; ni++) {
        const int n = ni * 8 + 2 * tig;
        *(float2*)(Og + (size_t)g * DMODEL + n) =
            make_float2(acc[ni][0] * inv0, acc[ni][1] * inv0);
        *(float2*)(Og + (size_t)(g + 8) * DMODEL + n) =
            make_float2(acc[ni][2] * inv1, acc[ni][3] * inv1);
    }
}

// ---------------------------------------------------------------------------
extern "C" void kernel_launch(void* const* d_in, const int* in_sizes, int n_in,
                              void* d_out, int out_size)
{
    (void)in_sizes; (void)n_in; (void)out_size;
    const float* query = (const float*)d_in[0];
    const float* key_  = (const float*)d_in[1];
    const float* value = (const float*)d_in[2];
    const float* q_w   = (const float*)d_in[3];
    const float* q_b   = (const float*)d_in[4];
    const float* k_w   = (const float*)d_in[5];
    const float* k_b   = (const float*)d_in[6];
    const float* v_w   = (const float*)d_in[7];
    const float* v_b   = (const float*)d_in[8];
    const float* o_w   = (const float*)d_in[9];
    const float* o_b   = (const float*)d_in[10];
    float* out = (float*)d_out;

    float *qp, *kp, *vp, *ap;
    cudaGetSymbolAddress((void**)&qp, g_q);
    cudaGetSymbolAddress((void**)&kp, g_k);
    cudaGetSymbolAddress((void**)&vp, g_v);
    cudaGetSymbolAddress((void**)&ap, g_attn);

    cudaFuncSetAttribute(gemm3_mma_kernel,
                         cudaFuncAttributeMaxDynamicSharedMemorySize,
                         GEMM_SMEM_BYTES);
    cudaFuncSetAttribute(attn_fa2_kernel,
                         cudaFuncAttributeMaxDynamicSharedMemorySize,
                         FATTN_SMEM_BYTES);

    // QKV projections: one batched launch (z = 0,1,2).
    gemm3_mma_kernel<<<dim3(8, 32, 3), 256, GEMM_SMEM_BYTES>>>(
        query, q_w, q_b, qp,
        key_,  k_w, k_b, kp,
        value, v_w, v_b, vp);

    attn_fa2_kernel<<<dim3(TSEQ / 128, NHEAD, BSZ), 256, FATTN_SMEM_BYTES>>>(qp, kp, vp, ap);

    // Output projection (z = 0 only).
    gemm3_mma_kernel<<<dim3(8, 32, 1), 256, GEMM_SMEM_BYTES>>>(
        ap, o_w, o_b, out,
        ap, o_w, o_b, out,
        ap, o_w, o_b, out);
}

// round 17
// speedup vs baseline: 1.6488x; 1.0667x over previous
#include <cuda_runtime.h>
#include <math.h>
#include <stdint.h>

#define BSZ   2
#define TSEQ  2048
#define DMODEL 1024
#define NHEAD 16
#define DHEAD 64
#define MROWS (BSZ * TSEQ)   // 4096

// Scratch (allocation-free rule: __device__ globals)
__device__ float g_q[MROWS * DMODEL];
__device__ float g_k[MROWS * DMODEL];
__device__ float g_v[MROWS * DMODEL];
__device__ float g_attn[MROWS * DMODEL];

__device__ __forceinline__ float tf32r(float x) {
    asm("cvt.rna.tf32.f32 %0, %0;" : "+f"(x));
    return x;
}

__device__ __forceinline__ float ex2(float x) {
    float r;
    asm("ex2.approx.ftz.f32 %0, %1;" : "=f"(r) : "f"(x));
    return r;
}

__device__ __forceinline__ void mma_tf32(float* c, const uint32_t* a, const uint32_t* b) {
    asm volatile(
        "mma.sync.aligned.m16n8k8.row.col.f32.tf32.tf32.f32 "
        "{%0,%1,%2,%3}, {%4,%5,%6,%7}, {%8,%9}, {%0,%1,%2,%3};"
        : "+f"(c[0]), "+f"(c[1]), "+f"(c[2]), "+f"(c[3])
        : "r"(a[0]), "r"(a[1]), "r"(a[2]), "r"(a[3]), "r"(b[0]), "r"(b[1]));
}

// ===========================================================================
// Tensor-core GEMM (tf32), BK=64 + L2 prefetch (round-16, 187us for QKV).
// ===========================================================================
#define GPITCH 68
#define GTENSOR_FLOATS (128 * GPITCH)              // 8704
#define GEMM_SMEM_BYTES (2 * GTENSOR_FLOATS * 4)   // 69,632 B

__global__ __launch_bounds__(256, 2) void gemm3_mma_kernel(
    const float* __restrict__ A0, const float* __restrict__ W0,
    const float* __restrict__ b0, float* __restrict__ C0,
    const float* __restrict__ A1, const float* __restrict__ W1,
    const float* __restrict__ b1, float* __restrict__ C1,
    const float* __restrict__ A2, const float* __restrict__ W2,
    const float* __restrict__ b2, float* __restrict__ C2)
{
    extern __shared__ float dsm[];
    float* As = dsm;
    float* Ws = dsm + GTENSOR_FLOATS;

    const int bz = blockIdx.z;
    const float* A    = (bz == 0) ? A0 : (bz == 1) ? A1 : A2;
    const float* W    = (bz == 0) ? W0 : (bz == 1) ? W1 : W2;
    const float* bias = (bz == 0) ? b0 : (bz == 1) ? b1 : b2;
    float*       C    = (bz == 0) ? C0 : (bz == 1) ? C1 : C2;

    const int tid = threadIdx.x;
    const int wid = tid >> 5;
    const int lid = tid & 31;
    const int bn  = blockIdx.x * 128;
    const int bm  = blockIdx.y * 128;
    const int wm  = (wid >> 2) * 64;
    const int wn  = (wid & 3) * 32;
    const int g   = lid >> 2;
    const int tig = lid & 3;

    float acc[4][4][4];
#pragma unroll
    for (int mi = 0; mi < 4; mi++)
#pragma unroll
        for (int ni = 0; ni < 4; ni++)
#pragma unroll
            for (int r = 0; r < 4; r++) acc[mi][ni][r] = 0.0f;

    const int prow = tid >> 1;
    const int pcol = (tid & 1) << 5;   // 0 or 32 (floats)

    for (int k0 = 0; k0 < DMODEL; k0 += 64) {
        if (k0) __syncthreads();
#pragma unroll
        for (int i = 0; i < 8; i++) {
            int v   = i * 256 + tid;
            int row = v >> 4;
            int c4  = (v & 15) << 2;
            float4 a = *(const float4*)(A + (size_t)(bm + row) * DMODEL + k0 + c4);
            a.x = tf32r(a.x); a.y = tf32r(a.y); a.z = tf32r(a.z); a.w = tf32r(a.w);
            *(float4*)&As[row * GPITCH + c4] = a;
            float4 w = *(const float4*)(W + (size_t)(bn + row) * DMODEL + k0 + c4);
            w.x = tf32r(w.x); w.y = tf32r(w.y); w.z = tf32r(w.z); w.w = tf32r(w.w);
            *(float4*)&Ws[row * GPITCH + c4] = w;
        }
        if (k0 + 64 < DMODEL) {
            asm volatile("prefetch.global.L2 [%0];"
                         :: "l"(A + (size_t)(bm + prow) * DMODEL + k0 + 64 + pcol));
            asm volatile("prefetch.global.L2 [%0];"
                         :: "l"(W + (size_t)(bn + prow) * DMODEL + k0 + 64 + pcol));
        }
        __syncthreads();

#pragma unroll
        for (int kk = 0; kk < 64; kk += 8) {
            uint32_t af[4][4], bf[4][2];
#pragma unroll
            for (int mi = 0; mi < 4; mi++) {
                const int m = wm + mi * 16 + g;
                af[mi][0] = __float_as_uint(As[m * GPITCH + kk + tig]);
                af[mi][1] = __float_as_uint(As[(m + 8) * GPITCH + kk + tig]);
                af[mi][2] = __float_as_uint(As[m * GPITCH + kk + tig + 4]);
                af[mi][3] = __float_as_uint(As[(m + 8) * GPITCH + kk + tig + 4]);
            }
#pragma unroll
            for (int ni = 0; ni < 4; ni++) {
                const int n = wn + ni * 8 + g;
                bf[ni][0] = __float_as_uint(Ws[n * GPITCH + kk + tig]);
                bf[ni][1] = __float_as_uint(Ws[n * GPITCH + kk + tig + 4]);
            }
#pragma unroll
            for (int mi = 0; mi < 4; mi++)
#pragma unroll
                for (int ni = 0; ni < 4; ni++)
                    mma_tf32(acc[mi][ni], af[mi], bf[ni]);
        }
    }

#pragma unroll
    for (int ni = 0; ni < 4; ni++) {
        const int n = bn + wn + ni * 8 + 2 * tig;
        const float bb0 = bias[n], bb1 = bias[n + 1];
#pragma unroll
        for (int mi = 0; mi < 4; mi++) {
            const int m0 = bm + wm + mi * 16 + g;
            float2 lo = make_float2(acc[mi][ni][0] + bb0, acc[mi][ni][1] + bb1);
            float2 hi = make_float2(acc[mi][ni][2] + bb0, acc[mi][ni][3] + bb1);
            *(float2*)(C + (size_t)m0 * DMODEL + n)       = lo;
            *(float2*)(C + (size_t)(m0 + 8) * DMODEL + n) = hi;
        }
    }
}

// ===========================================================================
// Causal flash attention, FA2-style, 2 CTAs/SM + LPT.
// CHANGE vs round 14: V staged NATURAL [k][d] at pitch 72 (no transpose
// stores -> no 8-way STS conflicts; PV B-frag reads bank-conflict-free:
// bank = 8*tig + g, all 32 lanes distinct). + L2 prefetch of next K/V tile.
// SMEM: Qs 128x68 + Ks 64x68 + Vs 64x72 + Ps 128x68 = 105,472 B.
// ===========================================================================
#define FPITCH 68
#define VPITCH 72
#define FQS_OFF 0                          // Qs[128][68]
#define FKS_OFF (128 * FPITCH)             // Ks[64][68]   natural [k][d]
#define FVS_OFF (FKS_OFF + 64 * FPITCH)    // Vs[64][72]   natural [k][d]
#define FPS_OFF (FVS_OFF + 64 * VPITCH)    // Ps[128][68]  per-warp P slabs
#define FATTN_SMEM_BYTES ((FPS_OFF + 128 * FPITCH) * 4)   // 105,472 B

__global__ __launch_bounds__(256, 2) void attn_fa2_kernel(
    const float* __restrict__ Q, const float* __restrict__ K,
    const float* __restrict__ V, float* __restrict__ O)
{
    extern __shared__ float sm[];
    float* Qs = sm + FQS_OFF;
    float* Ks = sm + FKS_OFF;
    float* Vs = sm + FVS_OFF;
    float* Ps = sm + FPS_OFF;

    const int qt  = (gridDim.x - 1) - blockIdx.x;   // LPT: heavy tiles first
    const int h   = blockIdx.y;
    const int b   = blockIdx.z;
    const int tid = threadIdx.x;
    const int wid = tid >> 5;
    const int lid = tid & 31;
    const int g   = lid >> 2;
    const int tig = lid & 3;
    const int wm  = wid * 16;
    const int q0  = qt * 128;

    const float SC = 0.18033688011f;   // (1/sqrt(64)) * log2(e)
    const float* Qg = Q + (size_t)(b * TSEQ + q0 + wm) * DMODEL + h * DHEAD;
#pragma unroll
    for (int i = 0; i < 8; i++) {
        int v   = i * 32 + lid;
        int row = v >> 4;
        int c4  = (v & 15) << 2;
        float4 t = *(const float4*)(Qg + (size_t)row * DMODEL + c4);
        t.x = tf32r(t.x * SC); t.y = tf32r(t.y * SC);
        t.z = tf32r(t.z * SC); t.w = tf32r(t.w * SC);
        *(float4*)&Qs[(wm + row) * FPITCH + c4] = t;
    }
    __syncwarp();

    float acc[8][4];
#pragma unroll
    for (int ni = 0; ni < 8; ni++)
#pragma unroll
        for (int r = 0; r < 4; r++) acc[ni][r] = 0.0f;

    float m0 = -1e30f, m1 = -1e30f, l0 = 0.0f, l1 = 0.0f;
    const int row0 = q0 + wm + g;

    const int n_kt = 2 * qt + 2;
    for (int kt = 0; kt < n_kt; kt++) {
        __syncthreads();
        const float* Kg = K + (size_t)(b * TSEQ + kt * 64) * DMODEL + h * DHEAD;
        const float* Vg = V + (size_t)(b * TSEQ + kt * 64) * DMODEL + h * DHEAD;
#pragma unroll
        for (int i = 0; i < 4; i++) {
            int v  = i * 256 + tid;
            int kr = v >> 4;
            int d4 = (v & 15) << 2;
            float4 t = *(const float4*)(Kg + (size_t)kr * DMODEL + d4);
            t.x = tf32r(t.x); t.y = tf32r(t.y); t.z = tf32r(t.z); t.w = tf32r(t.w);
            *(float4*)&Ks[kr * FPITCH + d4] = t;
            float4 u = *(const float4*)(Vg + (size_t)kr * DMODEL + d4);
            u.x = tf32r(u.x); u.y = tf32r(u.y); u.z = tf32r(u.z); u.w = tf32r(u.w);
            *(float4*)&Vs[kr * VPITCH + d4] = u;
        }
        // L2 prefetch next K/V tile (128 lines each; 256 threads cover both).
        if (kt + 1 < n_kt) {
            const float* nb = ((tid & 128) ? Vg : Kg) + (size_t)64 * DMODEL;
            asm volatile("prefetch.global.L2 [%0];"
                         :: "l"(nb + (size_t)(tid & 63) * DMODEL + ((tid >> 6) & 1) * 32));
        }
        __syncthreads();

        // ---- S = Q @ K^T ----
        float sacc[8][4];
#pragma unroll
        for (int ni = 0; ni < 8; ni++)
#pragma unroll
            for (int r = 0; r < 4; r++) sacc[ni][r] = 0.0f;

#pragma unroll
        for (int kk = 0; kk < 8; kk++) {
            uint32_t af[4];
            af[0] = __float_as_uint(Qs[(wm + g) * FPITCH + kk * 8 + tig]);
            af[1] = __float_as_uint(Qs[(wm + g + 8) * FPITCH + kk * 8 + tig]);
            af[2] = __float_as_uint(Qs[(wm + g) * FPITCH + kk * 8 + tig + 4]);
            af[3] = __float_as_uint(Qs[(wm + g + 8) * FPITCH + kk * 8 + tig + 4]);
#pragma unroll
            for (int ni = 0; ni < 8; ni++) {
                uint32_t bf[2];
                bf[0] = __float_as_uint(Ks[(ni * 8 + g) * FPITCH + kk * 8 + tig]);
                bf[1] = __float_as_uint(Ks[(ni * 8 + g) * FPITCH + kk * 8 + tig + 4]);
                mma_tf32(sacc[ni], af, bf);
            }
        }

        // ---- causal mask ----
        const int lim0 = row0 - kt * 64;
        const int lim1 = lim0 + 8;
#pragma unroll
        for (int ni = 0; ni < 8; ni++) {
            const int c0 = ni * 8 + 2 * tig;
            const int c1 = c0 + 1;
            if (c0 > lim0) sacc[ni][0] = -1e30f;
            if (c1 > lim0) sacc[ni][1] = -1e30f;
            if (c0 > lim1) sacc[ni][2] = -1e30f;
            if (c1 > lim1) sacc[ni][3] = -1e30f;
        }

        // ---- online softmax (registers + quad shfl) ----
        float mx0 = -1e30f, mx1 = -1e30f;
#pragma unroll
        for (int ni = 0; ni < 8; ni++) {
            mx0 = fmaxf(mx0, fmaxf(sacc[ni][0], sacc[ni][1]));
            mx1 = fmaxf(mx1, fmaxf(sacc[ni][2], sacc[ni][3]));
        }
        mx0 = fmaxf(mx0, __shfl_xor_sync(0xffffffffu, mx0, 1));
        mx0 = fmaxf(mx0, __shfl_xor_sync(0xffffffffu, mx0, 2));
        mx1 = fmaxf(mx1, __shfl_xor_sync(0xffffffffu, mx1, 1));
        mx1 = fmaxf(mx1, __shfl_xor_sync(0xffffffffu, mx1, 2));

        const float mn0 = fmaxf(m0, mx0);
        const float mn1 = fmaxf(m1, mx1);
        const float a0 = ex2(m0 - mn0);
        const float a1 = ex2(m1 - mn1);
        float ls0 = 0.0f, ls1 = 0.0f;
#pragma unroll
        for (int ni = 0; ni < 8; ni++) {
            float p0 = tf32r(ex2(sacc[ni][0] - mn0));
            float p1 = tf32r(ex2(sacc[ni][1] - mn0));
            float p2 = tf32r(ex2(sacc[ni][2] - mn1));
            float p3 = tf32r(ex2(sacc[ni][3] - mn1));
            sacc[ni][0] = p0; sacc[ni][1] = p1;
            sacc[ni][2] = p2; sacc[ni][3] = p3;
            ls0 += p0 + p1;
            ls1 += p2 + p3;
        }
        ls0 += __shfl_xor_sync(0xffffffffu, ls0, 1);
        ls0 += __shfl_xor_sync(0xffffffffu, ls0, 2);
        ls1 += __shfl_xor_sync(0xffffffffu, ls1, 1);
        ls1 += __shfl_xor_sync(0xffffffffu, ls1, 2);
        l0 = l0 * a0 + ls0;
        l1 = l1 * a1 + ls1;
        m0 = mn0; m1 = mn1;

        // rescale running O
#pragma unroll
        for (int ni = 0; ni < 8; ni++) {
            acc[ni][0] *= a0; acc[ni][1] *= a0;
            acc[ni][2] *= a1; acc[ni][3] *= a1;
        }

        // ---- P -> warp-private slab -> A fragments ----
#pragma unroll
        for (int ni = 0; ni < 8; ni++) {
            *(float2*)&Ps[(wm + g) * FPITCH + ni * 8 + 2 * tig] =
                make_float2(sacc[ni][0], sacc[ni][1]);
            *(float2*)&Ps[(wm + g + 8) * FPITCH + ni * 8 + 2 * tig] =
                make_float2(sacc[ni][2], sacc[ni][3]);
        }
        __syncwarp();

        // ---- O += P @ V : B-frags from NATURAL V (conflict-free) ----
#pragma unroll
        for (int kk = 0; kk < 8; kk++) {
            uint32_t af[4];
            af[0] = __float_as_uint(Ps[(wm + g) * FPITCH + kk * 8 + tig]);
            af[1] = __float_as_uint(Ps[(wm + g + 8) * FPITCH + kk * 8 + tig]);
            af[2] = __float_as_uint(Ps[(wm + g) * FPITCH + kk * 8 + tig + 4]);
            af[3] = __float_as_uint(Ps[(wm + g + 8) * FPITCH + kk * 8 + tig + 4]);
#pragma unroll
            for (int ni = 0; ni < 8; ni++) {
                uint32_t bf[2];
                bf[0] = __float_as_uint(Vs[(kk * 8 + tig) * VPITCH + ni * 8 + g]);
                bf[1] = __float_as_uint(Vs[(kk * 8 + tig + 4) * VPITCH + ni * 8 + g]);
                mma_tf32(acc[ni], af, bf);
            }
        }
        __syncwarp();
    }

    const float inv0 = 1.0f / l0;
    const float inv1 = 1.0f / l1;
    float* Og = O + (size_t)(b * TSEQ + q0 + wm) * DMODEL + h * DHEAD;
#pragma unroll
    for (int ni = 0; ni < 8; ni++) {
        const int n = ni * 8 + 2 * tig;
        *(float2*)(Og + (size_t)g * DMODEL + n) =
            make_float2(acc[ni][0] * inv0, acc[ni][1] * inv0);
        *(float2*)(Og + (size_t)(g + 8) * DMODEL + n) =
            make_float2(acc[ni][2] * inv1, acc[ni][3] * inv1);
    }
}

// ---------------------------------------------------------------------------
extern "C" void kernel_launch(void* const* d_in, const int* in_sizes, int n_in,
                              void* d_out, int out_size)
{
    (void)in_sizes; (void)n_in; (void)out_size;
    const float* query = (const float*)d_in[0];
    const float* key_  = (const float*)d_in[1];
    const float* value = (const float*)d_in[2];
    const float* q_w   = (const float*)d_in[3];
    const float* q_b   = (const float*)d_in[4];
    const float* k_w   = (const float*)d_in[5];
    const float* k_b   = (const float*)d_in[6];
    const float* v_w   = (const float*)d_in[7];
    const float* v_b   = (const float*)d_in[8];
    const float* o_w   = (const float*)d_in[9];
    const float* o_b   = (const float*)d_in[10];
    float* out = (float*)d_out;

    float *qp, *kp, *vp, *ap;
    cudaGetSymbolAddress((void**)&qp, g_q);
    cudaGetSymbolAddress((void**)&kp, g_k);
    cudaGetSymbolAddress((void**)&vp, g_v);
    cudaGetSymbolAddress((void**)&ap, g_attn);

    cudaFuncSetAttribute(gemm3_mma_kernel,
                         cudaFuncAttributeMaxDynamicSharedMemorySize,
                         GEMM_SMEM_BYTES);
    cudaFuncSetAttribute(attn_fa2_kernel,
                         cudaFuncAttributeMaxDynamicSharedMemorySize,
                         FATTN_SMEM_BYTES);

    // QKV projections: one batched launch (z = 0,1,2).
    gemm3_mma_kernel<<<dim3(8, 32, 3), 256, GEMM_SMEM_BYTES>>>(
        query, q_w, q_b, qp,
        key_,  k_w, k_b, kp,
        value, v_w, v_b, vp);

    attn_fa2_kernel<<<dim3(TSEQ / 128, NHEAD, BSZ), 256, FATTN_SMEM_BYTES>>>(qp, kp, vp, ap);

    // Output projection (z = 0 only).
    gemm3_mma_kernel<<<dim3(8, 32, 1), 256, GEMM_SMEM_BYTES>>>(
        ap, o_w, o_b, out,
        ap, o_w, o_b, out,
        ap, o_w, o_b, out);
}